// round 16
// baseline (speedup 1.0000x reference)
#include <cuda_runtime.h>
#include <cuda_bf16.h>
#include <mma.h>
#include <cstdint>

using namespace nvcuda;

#define BB   64
#define DD   2048
#define JJ   196
#define CC   128
#define NCLS 1000
#define JP   224        // softmax pitch (7 chunks of 32)

// Output packing (tuple concat, fp32): cpt | scores | cpt2 | updates
#define OFF_SCORES 8192
#define OFF_CPT2   72192
#define OFF_UPD    80384

// Device-global scratch (static; no runtime allocation)
__device__ __align__(16) __nv_bfloat16 g_Whi[CC * DD];
__device__ __align__(16) __nv_bfloat16 g_Wlo[CC * DD];
__device__ __align__(16) __nv_bfloat16 g_smh[BB * CC * JP];
__device__ __align__(16) __nv_bfloat16 g_sml[BB * CC * JP];
__device__ float g_cpt[BB * CC];
__device__ float g_asq[CC];
__device__ int   g_cnt[BB];

__device__ __forceinline__ uint32_t pack2(float a, float b) {
    __nv_bfloat162 p = __floats2bfloat162_rn(a, b);
    return *reinterpret_cast<uint32_t*>(&p);
}
__device__ __forceinline__ float bfrnd(float v) {
    return __bfloat162float(__float2bfloat16(v));
}
__device__ __forceinline__ uint32_t smem_u32(const void* p) {
    uint32_t a;
    asm("{ .reg .u64 t; cvta.to.shared.u64 t, %1; cvt.u32.u64 %0, t; }"
        : "=r"(a) : "l"(p));
    return a;
}
__device__ __forceinline__ void cpa(uint32_t dst, const void* src) {
    asm volatile("cp.async.cg.shared.global [%0], [%1], 16;" :: "r"(dst), "l"(src));
}
#define CP_COMMIT()  asm volatile("cp.async.commit_group;" ::: "memory")
#define CP_WAIT(n)   asm volatile("cp.async.wait_group %0;" :: "n"(n) : "memory")

// ---------------------------------------------------------------------------
// Prep: split W_land into bf16 hi/lo, a_sq[c], zero g_cpt + g_cnt.
// ---------------------------------------------------------------------------
__global__ __launch_bounds__(256) void k_prep(const float* __restrict__ Wl) {
    const int c = blockIdx.x, t = threadIdx.x;
    const float* row = Wl + (size_t)c * DD;
    float s = 0.f;
    #pragma unroll
    for (int it = 0; it < 2; it++) {
        int d = (t + it * 256) * 4;
        float4 v = *(const float4*)(row + d);
        float h0 = bfrnd(v.x), h1 = bfrnd(v.y), h2 = bfrnd(v.z), h3 = bfrnd(v.w);
        *(uint2*)&g_Whi[c * DD + d] = make_uint2(pack2(h0, h1), pack2(h2, h3));
        *(uint2*)&g_Wlo[c * DD + d] = make_uint2(pack2(v.x - h0, v.y - h1),
                                                 pack2(v.z - h2, v.w - h3));
        s += v.x * v.x + v.y * v.y + v.z * v.z + v.w * v.w;
    }
    __shared__ float red[8];
    #pragma unroll
    for (int o = 16; o; o >>= 1) s += __shfl_xor_sync(0xffffffffu, s, o);
    if ((t & 31) == 0) red[t >> 5] = s;
    __syncthreads();
    if (t == 0) {
        float a = 0.f;
        #pragma unroll
        for (int i = 0; i < 8; i++) a += red[i];
        g_asq[c] = a;
    }
    if (t < 64) g_cpt[c * 64 + t] = 0.f;
    if (t == 128 && c < BB) g_cnt[c] = 0;
}

// ---------------------------------------------------------------------------
// GEMM1 (wmma bf16 3-term): ab[c][j] = sum_d W[c][d]*x[b][d][j]
// Block M=128(c) x N=64(j), K=2048 as 32 chunks of 64, 2-stage single-sync.
// Epilogue: softmax + split-bf16 out + cpt atomics. The LAST block of each
// batch (atomic counter) then computes cpt/cpt2/scores — grid is one wave
// (256 blocks <= 296 slots), so this tail overlaps the wave drain.
// ---------------------------------------------------------------------------
#define P1    72
#define P1B   144
#define M1_AH 0
#define M1_AL 18432
#define M1_BH 36864
#define M1_BL 46080
#define M1_BUF 55296
#define M1_SMEM 110592
#define NCH1  32
#define LP    68
#define SCPT  (2 * CC * LP * 4)   // smem offset for s_cpt (past lg/lg1)

__global__ __launch_bounds__(256, 2) void k_mma1(const float* __restrict__ x,
                                                 const float* __restrict__ Wc,
                                                 const float* __restrict__ bc,
                                                 float* __restrict__ out) {
    extern __shared__ char smem[];
    __shared__ float s_asq[CC];
    __shared__ float s_mx[64], s_inv[64];
    __shared__ int s_last;

    const uint32_t sb = smem_u32(smem);
    const int tid = threadIdx.x, w = tid >> 5;
    const int wq = w & 3;                 // c-tile (0..3)
    const int wk = w >> 2;                // k-split half (0..1)
    const int b = blockIdx.y, j0 = blockIdx.x * 64;
    if (tid < CC) s_asq[tid] = g_asq[tid];

    const int brow = tid >> 2;            // B staging: 0..63 (k row)
    const int bcs  = (tid & 3) * 16;      // j col start

    wmma::fragment<wmma::accumulator, 16, 16, 16, float> acc[2][4];
    #pragma unroll
    for (int i = 0; i < 2; i++)
        #pragma unroll
        for (int j = 0; j < 4; j++) wmma::fill_fragment(acc[i][j], 0.f);

    float4 fb[4];
    auto ldgB = [&](int k0) {
        const float* xp = x + ((size_t)b * DD + k0 + brow) * JJ;
        #pragma unroll
        for (int q = 0; q < 4; q++) {
            int jg = j0 + bcs + q * 4;
            fb[q] = (jg < JJ) ? *(const float4*)(xp + jg)
                              : make_float4(0.f, 0.f, 0.f, 0.f);
        }
    };
    auto stsB = [&](char* base) {
        const float* f = (const float*)fb;
        uint32_t hh[8], ll[8];
        #pragma unroll
        for (int q = 0; q < 8; q++) {
            float a0 = f[2 * q], a1 = f[2 * q + 1];
            float h0 = bfrnd(a0), h1 = bfrnd(a1);
            hh[q] = pack2(h0, h1);
            ll[q] = pack2(a0 - h0, a1 - h1);
        }
        char* dh = base + M1_BH + brow * P1B + bcs * 2;
        char* dl = base + M1_BL + brow * P1B + bcs * 2;
        *(uint4*)(dh)      = make_uint4(hh[0], hh[1], hh[2], hh[3]);
        *(uint4*)(dh + 16) = make_uint4(hh[4], hh[5], hh[6], hh[7]);
        *(uint4*)(dl)      = make_uint4(ll[0], ll[1], ll[2], ll[3]);
        *(uint4*)(dl + 16) = make_uint4(ll[4], ll[5], ll[6], ll[7]);
    };
    auto issueA = [&](int ch) {
        const int k0 = ch * 64;
        const uint32_t base = sb + (uint32_t)(ch & 1) * M1_BUF;
        #pragma unroll
        for (int i = 0; i < 4; i++) {
            int u = tid + 256 * i, row = u >> 3, g = u & 7;
            cpa(base + M1_AH + row * P1B + g * 16, g_Whi + row * DD + k0 + g * 8);
            cpa(base + M1_AL + row * P1B + g * 16, g_Wlo + row * DD + k0 + g * 8);
        }
        CP_COMMIT();
    };

    // prologue: stage chunk 0
    ldgB(0);
    issueA(0);
    stsB(smem);

    for (int ch = 0; ch < NCH1; ch++) {
        CP_WAIT(0);
        __syncthreads();
        if (ch + 1 < NCH1) { ldgB((ch + 1) * 64); issueA(ch + 1); }

        const char* cbase = smem + (size_t)(ch & 1) * M1_BUF;
        const __nv_bfloat16* Ah = (const __nv_bfloat16*)(cbase + M1_AH);
        const __nv_bfloat16* Al = (const __nv_bfloat16*)(cbase + M1_AL);
        const __nv_bfloat16* Bh = (const __nv_bfloat16*)(cbase + M1_BH);
        const __nv_bfloat16* Bl = (const __nv_bfloat16*)(cbase + M1_BL);
        #pragma unroll
        for (int ks2 = 0; ks2 < 2; ks2++) {
            const int ks = wk * 2 + ks2;
            wmma::fragment<wmma::matrix_a, 16, 16, 16, __nv_bfloat16, wmma::row_major> ah[2], al[2];
            #pragma unroll
            for (int i = 0; i < 2; i++) {
                wmma::load_matrix_sync(ah[i], Ah + (wq * 32 + i * 16) * P1 + ks * 16, P1);
                wmma::load_matrix_sync(al[i], Al + (wq * 32 + i * 16) * P1 + ks * 16, P1);
            }
            #pragma unroll
            for (int j = 0; j < 4; j++) {
                wmma::fragment<wmma::matrix_b, 16, 16, 16, __nv_bfloat16, wmma::row_major> bh, bl;
                wmma::load_matrix_sync(bh, Bh + (ks * 16) * P1 + j * 16, P1);
                wmma::load_matrix_sync(bl, Bl + (ks * 16) * P1 + j * 16, P1);
                #pragma unroll
                for (int i = 0; i < 2; i++) {
                    wmma::mma_sync(acc[i][j], ah[i], bh, acc[i][j]);
                    wmma::mma_sync(acc[i][j], ah[i], bl, acc[i][j]);
                    wmma::mma_sync(acc[i][j], al[i], bh, acc[i][j]);
                }
            }
        }
        if (ch + 1 < NCH1) stsB(smem + (size_t)((ch + 1) & 1) * M1_BUF);
    }
    __syncthreads();   // protect smem reuse (epilogue vs last chunk compute)

    // ---- epilogue: sum k-split halves, logits = 2*ab - asq, softmax ----
    float* lg  = (float*)smem;            // [128][LP]
    float* lg1 = lg + CC * LP;            // second half
    {
        float* dst = (wk == 0) ? lg : lg1;
        #pragma unroll
        for (int i = 0; i < 2; i++)
            #pragma unroll
            for (int j = 0; j < 4; j++)
                wmma::store_matrix_sync(dst + (wq * 32 + i * 16) * LP + j * 16,
                                        acc[i][j], LP, wmma::mem_row_major);
    }
    __syncthreads();
    for (int u = tid; u < CC * 64; u += 256) {
        int c = u >> 6, j = u & 63;
        lg[c * LP + j] += lg1[c * LP + j];
    }
    __syncthreads();

    if (tid < 64) {
        int j = tid;
        float mx = -1e30f;
        for (int c = 0; c < CC; c++)
            mx = fmaxf(mx, 2.f * lg[c * LP + j] - s_asq[c]);
        float s = 0.f;
        for (int c = 0; c < CC; c++)
            s += __expf(2.f * lg[c * LP + j] - s_asq[c] - mx);
        s_mx[j] = mx;
        s_inv[j] = 1.f / s;
    }
    __syncthreads();

    {
        const int c = tid >> 1, half = tid & 1;
        const float aq = s_asq[c];
        const size_t base = ((size_t)(b * CC) + c) * JP;
        float csum = 0.f;
        #pragma unroll
        for (int jj = 0; jj < 32; jj += 2) {
            int j = half * 32 + jj;
            int jg = j0 + j;
            float p0 = 0.f, p1 = 0.f;
            if (jg < JJ)
                p0 = __expf(2.f * lg[c * LP + j] - aq - s_mx[j]) * s_inv[j];
            if (jg + 1 < JJ)
                p1 = __expf(2.f * lg[c * LP + j + 1] - aq - s_mx[j + 1]) * s_inv[j + 1];
            if (jg < JP) {
                float h0 = bfrnd(p0), h1 = bfrnd(p1);
                *(uint32_t*)&g_smh[base + jg] = pack2(p0, p1);
                *(uint32_t*)&g_sml[base + jg] = pack2(p0 - h0, p1 - h1);
            }
            csum += p0 + p1;
        }
        csum += __shfl_xor_sync(0xffffffffu, csum, 1);
        if (half == 0) atomicAdd(&g_cpt[b * CC + c], csum);
    }

    // ---- last block of this batch computes cpt/cpt2/scores ----
    __syncthreads();                       // all cpt atomics of this block done
    __threadfence();                       // publish before counter (release)
    if (tid == 0) s_last = (atomicAdd(&g_cnt[b], 1) == 3);
    __syncthreads();
    if (s_last) {
        float* s_cpt = (float*)(smem + SCPT);
        if (tid < CC) {
            float v = __ldcg(&g_cpt[b * CC + tid]) * (1.f / (float)JJ);
            s_cpt[tid] = v;
            out[(size_t)b * CC + tid]            = v;
            out[OFF_CPT2 + (size_t)b * CC + tid] = v;
        }
        __syncthreads();
        #pragma unroll
        for (int q4 = 0; q4 < 4; q4++) {
            int n = q4 * 256 + tid;
            if (n < NCLS) {
                const float4* wp = (const float4*)(Wc + (size_t)n * CC);
                float s = 0.f;
                #pragma unroll
                for (int q = 0; q < 32; q++) {
                    float4 wv = wp[q];
                    float4 cv = *(const float4*)&s_cpt[q * 4];
                    s += wv.x * cv.x + wv.y * cv.y + wv.z * cv.z + wv.w * cv.w;
                }
                out[OFF_SCORES + (size_t)b * NCLS + n] = s + bc[n];
            }
        }
    }
}

// ---------------------------------------------------------------------------
// GEMM2 (wmma bf16 3-term): updates[c][d] = sum_j sm[c][j]*x[b][d][j]
// Block M=128(c) x N=128(d), K=224 in 7 chunks of 32, 2-stage single-sync.
// Pure GEMM — no fused extras (proven in R13/R15 to cost more than they save).
// ---------------------------------------------------------------------------
#define PA 40
#define G2_AH 0
#define G2_AL 10240
#define G2_BH 20480
#define G2_BL 30720
#define G2_BUF 40960
#define G2_SMEM 81920

__global__ __launch_bounds__(256, 2) void k_mma2(const float* __restrict__ x,
                                                 float* __restrict__ out_upd) {
    extern __shared__ char smem[];
    const uint32_t sb = smem_u32(smem);
    const int tid = threadIdx.x, w = tid >> 5;
    const int wm = w & 3, wn = w >> 2;
    const int b = blockIdx.y, d0 = blockIdx.x * 128;

    const __nv_bfloat16* ah_g = g_smh + (size_t)b * CC * JP;
    const __nv_bfloat16* al_g = g_sml + (size_t)b * CC * JP;

    const int brow = tid >> 1;            // B staging: d row 0..127
    const int bcs  = (tid & 1) * 16;      // k col start

    wmma::fragment<wmma::accumulator, 16, 16, 16, float> acc[2][4];
    #pragma unroll
    for (int i = 0; i < 2; i++)
        #pragma unroll
        for (int j = 0; j < 4; j++) wmma::fill_fragment(acc[i][j], 0.f);

    float4 fb[4];
    auto ldgB = [&](int k0) {
        const float* xp = x + ((size_t)b * DD + d0 + brow) * JJ;
        #pragma unroll
        for (int q = 0; q < 4; q++) {
            int jg = k0 + bcs + q * 4;
            fb[q] = (jg < JJ) ? *(const float4*)(xp + jg)
                              : make_float4(0.f, 0.f, 0.f, 0.f);
        }
    };
    auto stsB = [&](char* base) {
        const float* f = (const float*)fb;
        uint32_t hh[8], ll[8];
        #pragma unroll
        for (int q = 0; q < 8; q++) {
            float a0 = f[2 * q], a1 = f[2 * q + 1];
            float h0 = bfrnd(a0), h1 = bfrnd(a1);
            hh[q] = pack2(h0, h1);
            ll[q] = pack2(a0 - h0, a1 - h1);
        }
        char* dh = base + G2_BH + brow * 80 + bcs * 2;
        char* dl = base + G2_BL + brow * 80 + bcs * 2;
        *(uint4*)(dh)      = make_uint4(hh[0], hh[1], hh[2], hh[3]);
        *(uint4*)(dh + 16) = make_uint4(hh[4], hh[5], hh[6], hh[7]);
        *(uint4*)(dl)      = make_uint4(ll[0], ll[1], ll[2], ll[3]);
        *(uint4*)(dl + 16) = make_uint4(ll[4], ll[5], ll[6], ll[7]);
    };
    auto issueA = [&](int ch) {
        const int k0 = ch * 32;
        const uint32_t base = sb + (uint32_t)(ch & 1) * G2_BUF;
        #pragma unroll
        for (int i = 0; i < 2; i++) {
            int u = tid + 256 * i, row = u >> 2, g = u & 3;
            cpa(base + G2_AH + row * 80 + g * 16, ah_g + (size_t)row * JP + k0 + g * 8);
            cpa(base + G2_AL + row * 80 + g * 16, al_g + (size_t)row * JP + k0 + g * 8);
        }
        CP_COMMIT();
    };

    ldgB(0);
    issueA(0);
    stsB(smem);

    for (int ch = 0; ch < 7; ch++) {
        CP_WAIT(0);
        __syncthreads();
        if (ch + 1 < 7) { ldgB((ch + 1) * 32); issueA(ch + 1); }

        const char* cbase = smem + (size_t)(ch & 1) * G2_BUF;
        const __nv_bfloat16* Ah = (const __nv_bfloat16*)(cbase + G2_AH);
        const __nv_bfloat16* Al = (const __nv_bfloat16*)(cbase + G2_AL);
        const __nv_bfloat16* Bh = (const __nv_bfloat16*)(cbase + G2_BH);
        const __nv_bfloat16* Bl = (const __nv_bfloat16*)(cbase + G2_BL);
        #pragma unroll
        for (int ks = 0; ks < 2; ks++) {
            wmma::fragment<wmma::matrix_a, 16, 16, 16, __nv_bfloat16, wmma::row_major> ah[2], al[2];
            #pragma unroll
            for (int i = 0; i < 2; i++) {
                wmma::load_matrix_sync(ah[i], Ah + (wm * 32 + i * 16) * PA + ks * 16, PA);
                wmma::load_matrix_sync(al[i], Al + (wm * 32 + i * 16) * PA + ks * 16, PA);
            }
            #pragma unroll
            for (int j = 0; j < 4; j++) {
                wmma::fragment<wmma::matrix_b, 16, 16, 16, __nv_bfloat16, wmma::col_major> bh, bl;
                wmma::load_matrix_sync(bh, Bh + (wn * 64 + j * 16) * PA + ks * 16, PA);
                wmma::load_matrix_sync(bl, Bl + (wn * 64 + j * 16) * PA + ks * 16, PA);
                #pragma unroll
                for (int i = 0; i < 2; i++) {
                    wmma::mma_sync(acc[i][j], ah[i], bh, acc[i][j]);
                    wmma::mma_sync(acc[i][j], ah[i], bl, acc[i][j]);
                    wmma::mma_sync(acc[i][j], al[i], bh, acc[i][j]);
                }
            }
        }
        if (ch + 1 < 7) stsB(smem + (size_t)((ch + 1) & 1) * G2_BUF);
    }

    #pragma unroll
    for (int i = 0; i < 2; i++) {
        int c0 = wm * 32 + i * 16;
        #pragma unroll
        for (int j = 0; j < 4; j++) {
            int dc = d0 + wn * 64 + j * 16;
            wmma::store_matrix_sync(out_upd + ((size_t)(b * CC) + c0) * DD + dc,
                                    acc[i][j], DD, wmma::mem_row_major);
        }
    }
}

// ---------------------------------------------------------------------------
extern "C" void kernel_launch(void* const* d_in, const int* in_sizes, int n_in,
                              void* d_out, int out_size) {
    const float* x  = (const float*)d_in[0];
    const float* Wl = (const float*)d_in[1];
    const float* Wc = (const float*)d_in[2];
    const float* bc = (const float*)d_in[3];
    float* out = (float*)d_out;

    cudaFuncSetAttribute(k_mma1, cudaFuncAttributeMaxDynamicSharedMemorySize, M1_SMEM);
    cudaFuncSetAttribute(k_mma2, cudaFuncAttributeMaxDynamicSharedMemorySize, G2_SMEM);

    k_prep<<<CC, 256>>>(Wl);
    k_mma1<<<dim3(4, BB), 256, M1_SMEM>>>(x, Wc, bc, out);
    k_mma2<<<dim3(16, BB), 256, G2_SMEM>>>(x, out + OFF_UPD);
}

// round 17
// speedup vs baseline: 1.2035x; 1.2035x over previous
#include <cuda_runtime.h>
#include <cuda_bf16.h>
#include <mma.h>
#include <cstdint>

using namespace nvcuda;

#define BB   64
#define DD   2048
#define JJ   196
#define CC   128
#define NCLS 1000
#define JP   224        // softmax pitch (7 chunks of 32)

// Output packing (tuple concat, fp32): cpt | scores | cpt2 | updates
#define OFF_SCORES 8192
#define OFF_CPT2   72192
#define OFF_UPD    80384

// Device-global scratch (static; no runtime allocation)
__device__ __align__(16) __nv_bfloat16 g_Whi[CC * DD];
__device__ __align__(16) __nv_bfloat16 g_Wlo[CC * DD];
__device__ __align__(16) __nv_bfloat16 g_smh[BB * CC * JP];
__device__ __align__(16) __nv_bfloat16 g_sml[BB * CC * JP];
__device__ float g_cpt[BB * CC];
__device__ float g_asq[CC];

__device__ __forceinline__ uint32_t pack2(float a, float b) {
    __nv_bfloat162 p = __floats2bfloat162_rn(a, b);
    return *reinterpret_cast<uint32_t*>(&p);
}
__device__ __forceinline__ float bfrnd(float v) {
    return __bfloat162float(__float2bfloat16(v));
}
__device__ __forceinline__ uint32_t smem_u32(const void* p) {
    uint32_t a;
    asm("{ .reg .u64 t; cvta.to.shared.u64 t, %1; cvt.u32.u64 %0, t; }"
        : "=r"(a) : "l"(p));
    return a;
}
__device__ __forceinline__ void cpa(uint32_t dst, const void* src) {
    asm volatile("cp.async.cg.shared.global [%0], [%1], 16;" :: "r"(dst), "l"(src));
}
#define CP_COMMIT()  asm volatile("cp.async.commit_group;" ::: "memory")
#define CP_WAIT(n)   asm volatile("cp.async.wait_group %0;" :: "n"(n) : "memory")

// ---------------------------------------------------------------------------
// Prep: split W_land into bf16 hi/lo, a_sq[c], zero g_cpt. 256 thr/block.
// ---------------------------------------------------------------------------
__global__ __launch_bounds__(256) void k_prep(const float* __restrict__ Wl) {
    const int c = blockIdx.x, t = threadIdx.x;
    const float* row = Wl + (size_t)c * DD;
    float s = 0.f;
    #pragma unroll
    for (int it = 0; it < 2; it++) {
        int d = (t + it * 256) * 4;
        float4 v = *(const float4*)(row + d);
        float h0 = bfrnd(v.x), h1 = bfrnd(v.y), h2 = bfrnd(v.z), h3 = bfrnd(v.w);
        *(uint2*)&g_Whi[c * DD + d] = make_uint2(pack2(h0, h1), pack2(h2, h3));
        *(uint2*)&g_Wlo[c * DD + d] = make_uint2(pack2(v.x - h0, v.y - h1),
                                                 pack2(v.z - h2, v.w - h3));
        s += v.x * v.x + v.y * v.y + v.z * v.z + v.w * v.w;
    }
    __shared__ float red[8];
    #pragma unroll
    for (int o = 16; o; o >>= 1) s += __shfl_xor_sync(0xffffffffu, s, o);
    if ((t & 31) == 0) red[t >> 5] = s;
    __syncthreads();
    if (t == 0) {
        float a = 0.f;
        #pragma unroll
        for (int i = 0; i < 8; i++) a += red[i];
        g_asq[c] = a;
    }
    if (t < 64) g_cpt[c * 64 + t] = 0.f;
}

// ---------------------------------------------------------------------------
// GEMM1 (wmma bf16 3-term): ab[c][j] = sum_d W[c][d]*x[b][d][j]
// Block M=128(c) x N=64(j), K=2048 as 32 chunks of 64, 2-stage single-sync.
// Pure GEMM + softmax epilogue — no fused extras (R13/R15/R16 all proved
// fusion into the GEMM kernels regresses).
// ---------------------------------------------------------------------------
#define P1    72
#define P1B   144
#define M1_AH 0
#define M1_AL 18432
#define M1_BH 36864
#define M1_BL 46080
#define M1_BUF 55296
#define M1_SMEM 110592
#define NCH1  32
#define LP    68

__global__ __launch_bounds__(256, 2) void k_mma1(const float* __restrict__ x) {
    extern __shared__ char smem[];
    __shared__ float s_asq[CC];
    __shared__ float s_mx[64], s_inv[64];

    const uint32_t sb = smem_u32(smem);
    const int tid = threadIdx.x, w = tid >> 5;
    const int wq = w & 3;                 // c-tile (0..3)
    const int wk = w >> 2;                // k-split half (0..1)
    const int b = blockIdx.y, j0 = blockIdx.x * 64;
    if (tid < CC) s_asq[tid] = g_asq[tid];

    const int brow = tid >> 2;            // B staging: 0..63 (k row)
    const int bcs  = (tid & 3) * 16;      // j col start

    wmma::fragment<wmma::accumulator, 16, 16, 16, float> acc[2][4];
    #pragma unroll
    for (int i = 0; i < 2; i++)
        #pragma unroll
        for (int j = 0; j < 4; j++) wmma::fill_fragment(acc[i][j], 0.f);

    float4 fb[4];
    auto ldgB = [&](int k0) {
        const float* xp = x + ((size_t)b * DD + k0 + brow) * JJ;
        #pragma unroll
        for (int q = 0; q < 4; q++) {
            int jg = j0 + bcs + q * 4;
            fb[q] = (jg < JJ) ? *(const float4*)(xp + jg)
                              : make_float4(0.f, 0.f, 0.f, 0.f);
        }
    };
    auto stsB = [&](char* base) {
        const float* f = (const float*)fb;
        uint32_t hh[8], ll[8];
        #pragma unroll
        for (int q = 0; q < 8; q++) {
            float a0 = f[2 * q], a1 = f[2 * q + 1];
            float h0 = bfrnd(a0), h1 = bfrnd(a1);
            hh[q] = pack2(h0, h1);
            ll[q] = pack2(a0 - h0, a1 - h1);
        }
        char* dh = base + M1_BH + brow * P1B + bcs * 2;
        char* dl = base + M1_BL + brow * P1B + bcs * 2;
        *(uint4*)(dh)      = make_uint4(hh[0], hh[1], hh[2], hh[3]);
        *(uint4*)(dh + 16) = make_uint4(hh[4], hh[5], hh[6], hh[7]);
        *(uint4*)(dl)      = make_uint4(ll[0], ll[1], ll[2], ll[3]);
        *(uint4*)(dl + 16) = make_uint4(ll[4], ll[5], ll[6], ll[7]);
    };
    auto issueA = [&](int ch) {
        const int k0 = ch * 64;
        const uint32_t base = sb + (uint32_t)(ch & 1) * M1_BUF;
        #pragma unroll
        for (int i = 0; i < 4; i++) {
            int u = tid + 256 * i, row = u >> 3, g = u & 7;
            cpa(base + M1_AH + row * P1B + g * 16, g_Whi + row * DD + k0 + g * 8);
            cpa(base + M1_AL + row * P1B + g * 16, g_Wlo + row * DD + k0 + g * 8);
        }
        CP_COMMIT();
    };

    // prologue: stage chunk 0
    ldgB(0);
    issueA(0);
    stsB(smem);

    for (int ch = 0; ch < NCH1; ch++) {
        CP_WAIT(0);
        __syncthreads();
        if (ch + 1 < NCH1) { ldgB((ch + 1) * 64); issueA(ch + 1); }

        const char* cbase = smem + (size_t)(ch & 1) * M1_BUF;
        const __nv_bfloat16* Ah = (const __nv_bfloat16*)(cbase + M1_AH);
        const __nv_bfloat16* Al = (const __nv_bfloat16*)(cbase + M1_AL);
        const __nv_bfloat16* Bh = (const __nv_bfloat16*)(cbase + M1_BH);
        const __nv_bfloat16* Bl = (const __nv_bfloat16*)(cbase + M1_BL);
        #pragma unroll
        for (int ks2 = 0; ks2 < 2; ks2++) {
            const int ks = wk * 2 + ks2;
            wmma::fragment<wmma::matrix_a, 16, 16, 16, __nv_bfloat16, wmma::row_major> ah[2], al[2];
            #pragma unroll
            for (int i = 0; i < 2; i++) {
                wmma::load_matrix_sync(ah[i], Ah + (wq * 32 + i * 16) * P1 + ks * 16, P1);
                wmma::load_matrix_sync(al[i], Al + (wq * 32 + i * 16) * P1 + ks * 16, P1);
            }
            #pragma unroll
            for (int j = 0; j < 4; j++) {
                wmma::fragment<wmma::matrix_b, 16, 16, 16, __nv_bfloat16, wmma::row_major> bh, bl;
                wmma::load_matrix_sync(bh, Bh + (ks * 16) * P1 + j * 16, P1);
                wmma::load_matrix_sync(bl, Bl + (ks * 16) * P1 + j * 16, P1);
                #pragma unroll
                for (int i = 0; i < 2; i++) {
                    wmma::mma_sync(acc[i][j], ah[i], bh, acc[i][j]);
                    wmma::mma_sync(acc[i][j], ah[i], bl, acc[i][j]);
                    wmma::mma_sync(acc[i][j], al[i], bh, acc[i][j]);
                }
            }
        }
        if (ch + 1 < NCH1) stsB(smem + (size_t)((ch + 1) & 1) * M1_BUF);
    }
    __syncthreads();   // protect smem reuse (epilogue vs last chunk compute)

    // ---- epilogue: sum k-split halves, logits = 2*ab - asq, softmax ----
    float* lg  = (float*)smem;            // [128][LP]
    float* lg1 = lg + CC * LP;            // second half
    {
        float* dst = (wk == 0) ? lg : lg1;
        #pragma unroll
        for (int i = 0; i < 2; i++)
            #pragma unroll
            for (int j = 0; j < 4; j++)
                wmma::store_matrix_sync(dst + (wq * 32 + i * 16) * LP + j * 16,
                                        acc[i][j], LP, wmma::mem_row_major);
    }
    __syncthreads();
    for (int u = tid; u < CC * 64; u += 256) {
        int c = u >> 6, j = u & 63;
        lg[c * LP + j] += lg1[c * LP + j];
    }
    __syncthreads();

    if (tid < 64) {
        int j = tid;
        float mx = -1e30f;
        for (int c = 0; c < CC; c++)
            mx = fmaxf(mx, 2.f * lg[c * LP + j] - s_asq[c]);
        float s = 0.f;
        for (int c = 0; c < CC; c++)
            s += __expf(2.f * lg[c * LP + j] - s_asq[c] - mx);
        s_mx[j] = mx;
        s_inv[j] = 1.f / s;
    }
    __syncthreads();

    {
        const int c = tid >> 1, half = tid & 1;
        const float aq = s_asq[c];
        const size_t base = ((size_t)(b * CC) + c) * JP;
        float csum = 0.f;
        #pragma unroll
        for (int jj = 0; jj < 32; jj += 2) {
            int j = half * 32 + jj;
            int jg = j0 + j;
            float p0 = 0.f, p1 = 0.f;
            if (jg < JJ)
                p0 = __expf(2.f * lg[c * LP + j] - aq - s_mx[j]) * s_inv[j];
            if (jg + 1 < JJ)
                p1 = __expf(2.f * lg[c * LP + j + 1] - aq - s_mx[j + 1]) * s_inv[j + 1];
            if (jg < JP) {
                float h0 = bfrnd(p0), h1 = bfrnd(p1);
                *(uint32_t*)&g_smh[base + jg] = pack2(p0, p1);
                *(uint32_t*)&g_sml[base + jg] = pack2(p0 - h0, p1 - h1);
            }
            csum += p0 + p1;
        }
        csum += __shfl_xor_sync(0xffffffffu, csum, 1);
        if (half == 0) atomicAdd(&g_cpt[b * CC + c], csum);
    }
}

// ---------------------------------------------------------------------------
// GEMM2 (wmma bf16 3-term): updates[c][d] = sum_j sm[c][j]*x[b][d][j]
// Block M=128(c) x N=128(d), K=224 in 7 chunks of 32, 2-stage single-sync.
// Pure GEMM — no fused extras.
// ---------------------------------------------------------------------------
#define PA 40
#define G2_AH 0
#define G2_AL 10240
#define G2_BH 20480
#define G2_BL 30720
#define G2_BUF 40960
#define G2_SMEM 81920

__global__ __launch_bounds__(256, 2) void k_mma2(const float* __restrict__ x,
                                                 float* __restrict__ out_upd) {
    extern __shared__ char smem[];
    const uint32_t sb = smem_u32(smem);
    const int tid = threadIdx.x, w = tid >> 5;
    const int wm = w & 3, wn = w >> 2;
    const int b = blockIdx.y, d0 = blockIdx.x * 128;

    const __nv_bfloat16* ah_g = g_smh + (size_t)b * CC * JP;
    const __nv_bfloat16* al_g = g_sml + (size_t)b * CC * JP;

    const int brow = tid >> 1;            // B staging: d row 0..127
    const int bcs  = (tid & 1) * 16;      // k col start

    wmma::fragment<wmma::accumulator, 16, 16, 16, float> acc[2][4];
    #pragma unroll
    for (int i = 0; i < 2; i++)
        #pragma unroll
        for (int j = 0; j < 4; j++) wmma::fill_fragment(acc[i][j], 0.f);

    float4 fb[4];
    auto ldgB = [&](int k0) {
        const float* xp = x + ((size_t)b * DD + d0 + brow) * JJ;
        #pragma unroll
        for (int q = 0; q < 4; q++) {
            int jg = k0 + bcs + q * 4;
            fb[q] = (jg < JJ) ? *(const float4*)(xp + jg)
                              : make_float4(0.f, 0.f, 0.f, 0.f);
        }
    };
    auto stsB = [&](char* base) {
        const float* f = (const float*)fb;
        uint32_t hh[8], ll[8];
        #pragma unroll
        for (int q = 0; q < 8; q++) {
            float a0 = f[2 * q], a1 = f[2 * q + 1];
            float h0 = bfrnd(a0), h1 = bfrnd(a1);
            hh[q] = pack2(h0, h1);
            ll[q] = pack2(a0 - h0, a1 - h1);
        }
        char* dh = base + G2_BH + brow * 80 + bcs * 2;
        char* dl = base + G2_BL + brow * 80 + bcs * 2;
        *(uint4*)(dh)      = make_uint4(hh[0], hh[1], hh[2], hh[3]);
        *(uint4*)(dh + 16) = make_uint4(hh[4], hh[5], hh[6], hh[7]);
        *(uint4*)(dl)      = make_uint4(ll[0], ll[1], ll[2], ll[3]);
        *(uint4*)(dl + 16) = make_uint4(ll[4], ll[5], ll[6], ll[7]);
    };
    auto issueA = [&](int ch) {
        const int k0 = ch * 32;
        const uint32_t base = sb + (uint32_t)(ch & 1) * G2_BUF;
        #pragma unroll
        for (int i = 0; i < 2; i++) {
            int u = tid + 256 * i, row = u >> 2, g = u & 3;
            cpa(base + G2_AH + row * 80 + g * 16, ah_g + (size_t)row * JP + k0 + g * 8);
            cpa(base + G2_AL + row * 80 + g * 16, al_g + (size_t)row * JP + k0 + g * 8);
        }
        CP_COMMIT();
    };

    ldgB(0);
    issueA(0);
    stsB(smem);

    for (int ch = 0; ch < 7; ch++) {
        CP_WAIT(0);
        __syncthreads();
        if (ch + 1 < 7) { ldgB((ch + 1) * 32); issueA(ch + 1); }

        const char* cbase = smem + (size_t)(ch & 1) * G2_BUF;
        const __nv_bfloat16* Ah = (const __nv_bfloat16*)(cbase + G2_AH);
        const __nv_bfloat16* Al = (const __nv_bfloat16*)(cbase + G2_AL);
        const __nv_bfloat16* Bh = (const __nv_bfloat16*)(cbase + G2_BH);
        const __nv_bfloat16* Bl = (const __nv_bfloat16*)(cbase + G2_BL);
        #pragma unroll
        for (int ks = 0; ks < 2; ks++) {
            wmma::fragment<wmma::matrix_a, 16, 16, 16, __nv_bfloat16, wmma::row_major> ah[2], al[2];
            #pragma unroll
            for (int i = 0; i < 2; i++) {
                wmma::load_matrix_sync(ah[i], Ah + (wm * 32 + i * 16) * PA + ks * 16, PA);
                wmma::load_matrix_sync(al[i], Al + (wm * 32 + i * 16) * PA + ks * 16, PA);
            }
            #pragma unroll
            for (int j = 0; j < 4; j++) {
                wmma::fragment<wmma::matrix_b, 16, 16, 16, __nv_bfloat16, wmma::col_major> bh, bl;
                wmma::load_matrix_sync(bh, Bh + (wn * 64 + j * 16) * PA + ks * 16, PA);
                wmma::load_matrix_sync(bl, Bl + (wn * 64 + j * 16) * PA + ks * 16, PA);
                #pragma unroll
                for (int i = 0; i < 2; i++) {
                    wmma::mma_sync(acc[i][j], ah[i], bh, acc[i][j]);
                    wmma::mma_sync(acc[i][j], ah[i], bl, acc[i][j]);
                    wmma::mma_sync(acc[i][j], al[i], bh, acc[i][j]);
                }
            }
        }
        if (ch + 1 < 7) stsB(smem + (size_t)((ch + 1) & 1) * G2_BUF);
    }

    #pragma unroll
    for (int i = 0; i < 2; i++) {
        int c0 = wm * 32 + i * 16;
        #pragma unroll
        for (int j = 0; j < 4; j++) {
            int dc = d0 + wn * 64 + j * 16;
            wmma::store_matrix_sync(out_upd + ((size_t)(b * CC) + c0) * DD + dc,
                                    acc[i][j], DD, wmma::mem_row_major);
        }
    }
}

// ---------------------------------------------------------------------------
// Finalize: cpt mean, cpt2, scores = cpt @ W_cls^T + b. Grid (4, 64)
// (R12 shape — measured 13.2us vs 16.6us for the 48-block variant).
// ---------------------------------------------------------------------------
__global__ __launch_bounds__(256) void k_scores(const float* __restrict__ Wc,
                                                const float* __restrict__ bc,
                                                float* __restrict__ out) {
    __shared__ float s_cpt[CC];
    const int b = blockIdx.y, nt = blockIdx.x, tid = threadIdx.x;
    if (tid < CC) {
        float v = g_cpt[b * CC + tid] * (1.f / (float)JJ);
        s_cpt[tid] = v;
        if (nt == 0) {
            out[(size_t)b * CC + tid]            = v;
            out[OFF_CPT2 + (size_t)b * CC + tid] = v;
        }
    }
    __syncthreads();
    const int n = nt * 250 + tid;
    if (tid < 250) {
        const float4* wp = (const float4*)(Wc + (size_t)n * CC);
        float s = 0.f;
        #pragma unroll
        for (int q = 0; q < 32; q++) {
            float4 wv = wp[q];
            float4 cv = *(const float4*)&s_cpt[q * 4];
            s += wv.x * cv.x + wv.y * cv.y + wv.z * cv.z + wv.w * cv.w;
        }
        out[OFF_SCORES + (size_t)b * NCLS + n] = s + bc[n];
    }
}

// ---------------------------------------------------------------------------
extern "C" void kernel_launch(void* const* d_in, const int* in_sizes, int n_in,
                              void* d_out, int out_size) {
    const float* x  = (const float*)d_in[0];
    const float* Wl = (const float*)d_in[1];
    const float* Wc = (const float*)d_in[2];
    const float* bc = (const float*)d_in[3];
    float* out = (float*)d_out;

    cudaFuncSetAttribute(k_mma1, cudaFuncAttributeMaxDynamicSharedMemorySize, M1_SMEM);
    cudaFuncSetAttribute(k_mma2, cudaFuncAttributeMaxDynamicSharedMemorySize, G2_SMEM);

    k_prep  <<<CC, 256>>>(Wl);
    k_mma1  <<<dim3(4, BB), 256, M1_SMEM>>>(x);
    k_mma2  <<<dim3(16, BB), 256, G2_SMEM>>>(x, out + OFF_UPD);
    k_scores<<<dim3(4, BB), 256>>>(Wc, bc, out);
}